// round 1
// baseline (speedup 1.0000x reference)
#include <cuda_runtime.h>
#include <math.h>

#define Bn 12
#define HW1 45056           // 128*352
#define N5 11264            // 64*176
#define W5i 176
#define BEVC 64
#define OUT_MAIN (12*128*128*128)   // 25165824

// BEV scratch, channels-last: [B][128][128][64]
__device__ float g_bev[Bn * 128 * 128 * BEVC];

// ---------------------------------------------------------------------------
// Kernel A: fused skip path.  skip = relu(bn2( relu(bn1(stage1 @ W1)) @ W2 ))
// one thread per pixel; weights transposed in shared, float4 broadcast loads.
// ---------------------------------------------------------------------------
__global__ __launch_bounds__(128, 4)
void kA(const float* __restrict__ stage1,
        const float* __restrict__ w1, const float* __restrict__ g1, const float* __restrict__ b1,
        const float* __restrict__ w2, const float* __restrict__ g2, const float* __restrict__ b2,
        float* __restrict__ skip_out)
{
    __shared__ float w1T[64*64];   // [c][o]
    __shared__ float w2T[64*32];   // [o][s]
    __shared__ float sg1[64], sb1[64], sg2[32], sb2[32];
    int tid = threadIdx.x;
    for (int i = tid; i < 64*64; i += 128) { int o = i & 63, c = i >> 6; w1T[c*64+o] = w1[o*64+c]; }
    for (int i = tid; i < 64*32; i += 128) { int s = i & 31, o = i >> 5; w2T[o*32+s] = w2[s*64+o]; }
    if (tid < 64) { sg1[tid] = g1[tid]; sb1[tid] = b1[tid]; }
    if (tid < 32) { sg2[tid] = g2[tid]; sb2[tid] = b2[tid]; }
    __syncthreads();

    int gid = blockIdx.x * 128 + tid;        // < 540672, exact
    int b = gid / HW1;
    int p = gid - b * HW1;
    const float* xin = stage1 + (size_t)b * 64 * HW1 + p;

    float acc[64];
    #pragma unroll
    for (int o = 0; o < 64; o++) acc[o] = 0.f;

    const float4* w1T4 = (const float4*)w1T;
    for (int c = 0; c < 64; c++) {
        float xv = xin[(size_t)c * HW1];
        #pragma unroll
        for (int o4 = 0; o4 < 16; o4++) {
            float4 w = w1T4[c*16 + o4];
            acc[o4*4+0] += xv * w.x;
            acc[o4*4+1] += xv * w.y;
            acc[o4*4+2] += xv * w.z;
            acc[o4*4+3] += xv * w.w;
        }
    }

    float sacc[32];
    #pragma unroll
    for (int s = 0; s < 32; s++) sacc[s] = 0.f;
    const float4* w2T4 = (const float4*)w2T;
    #pragma unroll
    for (int o = 0; o < 64; o++) {
        float v = fmaxf(acc[o] * sg1[o] + sb1[o], 0.f);
        #pragma unroll
        for (int s4 = 0; s4 < 8; s4++) {
            float4 w = w2T4[o*8 + s4];
            sacc[s4*4+0] += v * w.x;
            sacc[s4*4+1] += v * w.y;
            sacc[s4*4+2] += v * w.z;
            sacc[s4*4+3] += v * w.w;
        }
    }
    float* op = skip_out + (size_t)b * 32 * HW1 + p;
    #pragma unroll
    for (int s = 0; s < 32; s++)
        op[(size_t)s * HW1] = fmaxf(sacc[s] * sg2[s] + sb2[s], 0.f);
}

// ---------------------------------------------------------------------------
// Kernel B: fused lift. reduced(64) + depth logits(48) GEMM over 512 channels,
// softmax*10 -> depth, unproject, ego transform, scatter-add to g_bev.
// ---------------------------------------------------------------------------
__global__ __launch_bounds__(128, 2)
void kB(const float* __restrict__ stage5,
        const float* __restrict__ w5, const float* __restrict__ g5, const float* __restrict__ b5,
        const float* __restrict__ wd, const float* __restrict__ gd, const float* __restrict__ bd,
        const float* __restrict__ intr, const float* __restrict__ extr)
{
    __shared__ float ws[64*112];   // [c][o], o in 0..111 (64 reduced + 48 depth)
    int tid = threadIdx.x;
    int b = blockIdx.x / 88;
    int p = (blockIdx.x - b * 88) * 128 + tid;    // < 11264, exact
    const float* xin = stage5 + (size_t)b * 512 * N5 + p;

    float acc[112];
    #pragma unroll
    for (int i = 0; i < 112; i++) acc[i] = 0.f;

    for (int c0 = 0; c0 < 512; c0 += 64) {
        __syncthreads();
        for (int i = tid; i < 64*112; i += 128) {
            int o = i % 112; int c = i / 112;
            ws[c*112 + o] = (o < 64) ? w5[o*512 + c0 + c] : wd[(o-64)*512 + c0 + c];
        }
        __syncthreads();
        const float4* ws4 = (const float4*)ws;
        for (int c = 0; c < 64; c++) {
            float xv = xin[(size_t)(c0 + c) * N5];
            #pragma unroll
            for (int o4 = 0; o4 < 28; o4++) {
                float4 w = ws4[c*28 + o4];
                acc[o4*4+0] += xv * w.x;
                acc[o4*4+1] += xv * w.y;
                acc[o4*4+2] += xv * w.z;
                acc[o4*4+3] += xv * w.w;
            }
        }
    }

    // reduced = relu(bn(acc[0:64]))
    #pragma unroll
    for (int o = 0; o < 64; o++)
        acc[o] = fmaxf(acc[o] * g5[o] + b5[o], 0.f);

    // depth logits -> softmax(10*l) -> expected depth over log bins
    float m = -1e30f;
    #pragma unroll
    for (int j = 0; j < 48; j++) {
        float l = acc[64+j] * gd[j] + bd[j];
        acc[64+j] = 10.f * l;
        m = fmaxf(m, acc[64+j]);
    }
    const float lstep = 0.08711371545f;  // ln(60)/47
    float sum = 0.f, dsum = 0.f;
    #pragma unroll
    for (int j = 0; j < 48; j++) {
        float e = __expf(acc[64+j] - m);
        sum  += e;
        dsum += e * __expf((float)j * lstep);
    }
    float depth = dsum / sum;
    depth = fminf(fmaxf(depth, 1.0f), 65.0f);

    // unproject: K^{-1} via adjugate
    const float* K = intr + b * 9;
    float a00=K[0],a01=K[1],a02=K[2],a10=K[3],a11=K[4],a12=K[5],a20=K[6],a21=K[7],a22=K[8];
    float det = a00*(a11*a22 - a12*a21) - a01*(a10*a22 - a12*a20) + a02*(a10*a21 - a11*a20);
    float id = 1.0f / det;
    float i00 = (a11*a22 - a12*a21) * id;
    float i01 = (a02*a21 - a01*a22) * id;
    float i02 = (a01*a12 - a02*a11) * id;
    float i10 = (a12*a20 - a10*a22) * id;
    float i11 = (a00*a22 - a02*a20) * id;
    float i12 = (a02*a10 - a00*a12) * id;
    float i20 = (a10*a21 - a11*a20) * id;
    float i21 = (a01*a20 - a00*a21) * id;
    float i22 = (a00*a11 - a01*a10) * id;

    float py = (float)(p / W5i);
    float px = (float)(p - (p / W5i) * W5i);
    float cx = depth * (i00*px + i01*py + i02);
    float cy = depth * (i10*px + i11*py + i12);
    float cz = depth * (i20*px + i21*py + i22);

    const float* T = extr + b * 16;
    float ex = T[0]*cx + T[1]*cy + T[2]*cz  + T[3];
    float ey = T[4]*cx + T[5]*cy + T[6]*cz  + T[7];
    float ez = T[8]*cx + T[9]*cy + T[10]*cz + T[11];

    bool ev = (ex >= -51.2f) & (ex < 51.2f) & (ey >= -51.2f) & (ey < 51.2f)
            & (ez >= -5.0f)  & (ez < 3.0f);
    int bx = (int)floorf(ex / 0.4f + 64.0f);
    int by = (int)floorf(ey / 0.4f + 64.0f);
    bool gv = (bx >= 0) & (bx < 128) & (by >= 0) & (by < 128);
    if (ev & gv) {
        float wf = __expf(-0.05f * fabsf(ez));
        float* cell = g_bev + (((size_t)b * 128 + by) * 128 + bx) * BEVC;
        #pragma unroll
        for (int o = 0; o < 64; o++)
            atomicAdd(cell + o, acc[o] * wf);
    }
}

// ---------------------------------------------------------------------------
// Kernel C: 3x3 conv (64->128) on BEV + BN + ReLU.  Channels-last input tile
// in shared (conflict-free [ic][cell] layout) + 32-oc weight tile in shared.
// ---------------------------------------------------------------------------
__global__ __launch_bounds__(256, 1)
void kC(const float* __restrict__ w, const float* __restrict__ g, const float* __restrict__ bb,
        float* __restrict__ out)
{
    extern __shared__ float sm[];
    float* sin_ = sm;               // [ic 64][cell 340]  (10 x 34 tile)
    float* wsh  = sm + 64*340;      // [(kk*64+ic)*32 + ocl]
    int tid = threadIdx.x;
    int tx = tid & 31, ty = tid >> 5;
    int x0 = blockIdx.x * 32, y0 = blockIdx.y * 8;
    int bz = blockIdx.z;
    int b = bz >> 2;
    int oc0 = (bz & 3) * 32;

    // weights -> shared
    for (int i = tid; i < 18432; i += 256) {
        int ocl = i & 31;
        int t = i >> 5;
        int ic = t & 63;
        int kk = t >> 6;
        wsh[i] = w[((oc0 + ocl) * 64 + ic) * 9 + kk];
    }
    // input tile (with halo, zero padded) -> shared
    const float4* bev4 = (const float4*)g_bev;
    for (int i = tid; i < 5440; i += 256) {           // 340 cells * 16 float4
        int icg = i & 15;
        int cell = i >> 4;
        int iy = cell / 34, ix = cell - iy * 34;
        int gy = y0 + iy - 1, gx = x0 + ix - 1;
        float4 v = make_float4(0.f, 0.f, 0.f, 0.f);
        if (gy >= 0 && gy < 128 && gx >= 0 && gx < 128)
            v = bev4[((((size_t)b * 128 + gy) * 128 + gx) << 4) + icg];
        sin_[(icg*4+0)*340 + cell] = v.x;
        sin_[(icg*4+1)*340 + cell] = v.y;
        sin_[(icg*4+2)*340 + cell] = v.z;
        sin_[(icg*4+3)*340 + cell] = v.w;
    }
    __syncthreads();

    float acc[32];
    #pragma unroll
    for (int o = 0; o < 32; o++) acc[o] = 0.f;
    const float4* wsh4 = (const float4*)wsh;

    for (int ky = 0; ky < 3; ky++) {
        for (int kx = 0; kx < 3; kx++) {
            int base = (ty + ky) * 34 + tx + kx;
            int kk = ky * 3 + kx;
            #pragma unroll 4
            for (int ic = 0; ic < 64; ic++) {
                float xv = sin_[ic * 340 + base];
                #pragma unroll
                for (int o4 = 0; o4 < 8; o4++) {
                    float4 wv = wsh4[(kk*64 + ic)*8 + o4];
                    acc[o4*4+0] += xv * wv.x;
                    acc[o4*4+1] += xv * wv.y;
                    acc[o4*4+2] += xv * wv.z;
                    acc[o4*4+3] += xv * wv.w;
                }
            }
        }
    }

    float* op = out + (((size_t)b * 128 + oc0) * 128 + (y0 + ty)) * 128 + (x0 + tx);
    #pragma unroll
    for (int o = 0; o < 32; o++) {
        float r = fmaxf(acc[o] * g[oc0 + o] + bb[oc0 + o], 0.f);
        op[(size_t)o * 16384] = r;
    }
}

// ---------------------------------------------------------------------------
extern "C" void kernel_launch(void* const* d_in, const int* in_sizes, int n_in,
                              void* d_out, int out_size)
{
    const float* stage1 = (const float*)d_in[0];
    const float* stage5 = (const float*)d_in[1];
    const float* intr   = (const float*)d_in[2];
    const float* extr   = (const float*)d_in[3];
    const float* red1_w = (const float*)d_in[4];
    const float* red1_g = (const float*)d_in[5];
    const float* red1_b = (const float*)d_in[6];
    const float* skip_w = (const float*)d_in[7];
    const float* skip_g = (const float*)d_in[8];
    const float* skip_b = (const float*)d_in[9];
    const float* red5_w = (const float*)d_in[10];
    const float* red5_g = (const float*)d_in[11];
    const float* red5_b = (const float*)d_in[12];
    const float* dep5_w = (const float*)d_in[13];
    const float* dep5_g = (const float*)d_in[14];
    const float* dep5_b = (const float*)d_in[15];
    const float* main_w = (const float*)d_in[16];
    const float* main_g = (const float*)d_in[17];
    const float* main_b = (const float*)d_in[18];

    float* out_main = (float*)d_out;
    float* out_skip = (float*)d_out + OUT_MAIN;

    // zero BEV scratch
    void* bevPtr = nullptr;
    cudaGetSymbolAddress(&bevPtr, g_bev);
    cudaMemsetAsync(bevPtr, 0, sizeof(float) * (size_t)Bn * 128 * 128 * BEVC);

    // skip path
    kA<<<(Bn * HW1) / 128, 128>>>(stage1, red1_w, red1_g, red1_b,
                                  skip_w, skip_g, skip_b, out_skip);

    // lift + scatter
    kB<<<Bn * 88, 128>>>(stage5, red5_w, red5_g, red5_b,
                         dep5_w, dep5_g, dep5_b, intr, extr);

    // BEV conv
    static int kc_smem_set = 0;
    int smem = (64*340 + 18432) * sizeof(float);   // 160768
    cudaFuncSetAttribute(kC, cudaFuncAttributeMaxDynamicSharedMemorySize, smem);
    (void)kc_smem_set;
    dim3 gridC(4, 16, Bn * 4);
    kC<<<gridC, 256, smem>>>(main_w, main_g, main_b, out_main);
}

// round 2
// speedup vs baseline: 1.0807x; 1.0807x over previous
#include <cuda_runtime.h>
#include <math.h>

#define Bn 12
#define HW1 45056           // 128*352
#define N5 11264            // 64*176
#define W5i 176
#define BEVC 64
#define OUT_MAIN (12*128*128*128)   // 25165824

typedef unsigned long long u64;

// packed f32x2 helpers (sm_103a)
__device__ __forceinline__ u64 pack2(float lo, float hi) {
    u64 r; asm("mov.b64 %0, {%1, %2};" : "=l"(r) : "f"(lo), "f"(hi)); return r;
}
__device__ __forceinline__ void fma2(u64 &d, u64 a, u64 b) {
    asm("fma.rn.f32x2 %0, %1, %2, %0;" : "+l"(d) : "l"(a), "l"(b));
}
__device__ __forceinline__ float2 unpack2(u64 v) {
    float2 r; asm("mov.b64 {%0, %1}, %2;" : "=f"(r.x), "=f"(r.y) : "l"(v)); return r;
}

// BEV scratch, channels-last: [B][128][128][64]
__device__ float g_bev[Bn * 128 * 128 * BEVC];

// ---------------------------------------------------------------------------
// Kernel A: fused skip path.  skip = relu(bn2( relu(bn1(stage1 @ W1)) @ W2 ))
// f32x2 accumulators over output-channel pairs.
// ---------------------------------------------------------------------------
__global__ __launch_bounds__(128, 4)
void kA(const float* __restrict__ stage1,
        const float* __restrict__ w1, const float* __restrict__ g1, const float* __restrict__ b1,
        const float* __restrict__ w2, const float* __restrict__ g2, const float* __restrict__ b2,
        float* __restrict__ skip_out)
{
    __shared__ __align__(16) float w1T[64*64];   // [c][o]
    __shared__ __align__(16) float w2T[64*32];   // [o][s]
    __shared__ float sg1[64], sb1[64], sg2[32], sb2[32];
    int tid = threadIdx.x;
    for (int i = tid; i < 64*64; i += 128) { int o = i & 63, c = i >> 6; w1T[c*64+o] = w1[o*64+c]; }
    for (int i = tid; i < 64*32; i += 128) { int s = i & 31, o = i >> 5; w2T[o*32+s] = w2[s*64+o]; }
    if (tid < 64) { sg1[tid] = g1[tid]; sb1[tid] = b1[tid]; }
    if (tid < 32) { sg2[tid] = g2[tid]; sb2[tid] = b2[tid]; }
    __syncthreads();

    int gid = blockIdx.x * 128 + tid;        // < 540672, exact
    int b = gid / HW1;
    int p = gid - b * HW1;
    const float* xin = stage1 + (size_t)b * 64 * HW1 + p;

    u64 acc2[32];
    #pragma unroll
    for (int q = 0; q < 32; q++) acc2[q] = 0ull;

    const ulonglong2* w1T2 = (const ulonglong2*)w1T;   // 16 per channel
    for (int c = 0; c < 64; c++) {
        float xv = xin[(size_t)c * HW1];
        u64 xv2 = pack2(xv, xv);
        #pragma unroll
        for (int q = 0; q < 16; q++) {
            ulonglong2 wp = w1T2[c*16 + q];
            fma2(acc2[q*2+0], xv2, wp.x);
            fma2(acc2[q*2+1], xv2, wp.y);
        }
    }

    u64 sacc2[16];
    #pragma unroll
    for (int s = 0; s < 16; s++) sacc2[s] = 0ull;
    const ulonglong2* w2T2 = (const ulonglong2*)w2T;   // 8 per o
    #pragma unroll
    for (int q = 0; q < 32; q++) {
        float2 a = unpack2(acc2[q]);
        int o = 2*q;
        float v0 = fmaxf(a.x * sg1[o]   + sb1[o],   0.f);
        float v1 = fmaxf(a.y * sg1[o+1] + sb1[o+1], 0.f);
        u64 v0p = pack2(v0, v0);
        u64 v1p = pack2(v1, v1);
        #pragma unroll
        for (int s4 = 0; s4 < 8; s4++) {
            ulonglong2 wp0 = w2T2[o*8 + s4];
            fma2(sacc2[s4*2+0], v0p, wp0.x);
            fma2(sacc2[s4*2+1], v0p, wp0.y);
        }
        #pragma unroll
        for (int s4 = 0; s4 < 8; s4++) {
            ulonglong2 wp1 = w2T2[(o+1)*8 + s4];
            fma2(sacc2[s4*2+0], v1p, wp1.x);
            fma2(sacc2[s4*2+1], v1p, wp1.y);
        }
    }
    float* op = skip_out + (size_t)b * 32 * HW1 + p;
    #pragma unroll
    for (int s = 0; s < 16; s++) {
        float2 a = unpack2(sacc2[s]);
        op[(size_t)(2*s+0) * HW1] = fmaxf(a.x * sg2[2*s+0] + sb2[2*s+0], 0.f);
        op[(size_t)(2*s+1) * HW1] = fmaxf(a.y * sg2[2*s+1] + sb2[2*s+1], 0.f);
    }
}

// ---------------------------------------------------------------------------
// Kernel B: fused lift. reduced(64) + depth logits(48) GEMM over 512 channels,
// softmax*10 -> depth, unproject, ego transform, scatter-add to g_bev.
// ---------------------------------------------------------------------------
__global__ __launch_bounds__(128, 2)
void kB(const float* __restrict__ stage5,
        const float* __restrict__ w5, const float* __restrict__ g5, const float* __restrict__ b5,
        const float* __restrict__ wd, const float* __restrict__ gd, const float* __restrict__ bd,
        const float* __restrict__ intr, const float* __restrict__ extr)
{
    __shared__ __align__(16) float ws[64*112];   // [c][o], o in 0..111 (64 reduced + 48 depth)
    int tid = threadIdx.x;
    int b = blockIdx.x / 88;
    int p = (blockIdx.x - b * 88) * 128 + tid;    // < 11264, exact
    const float* xin = stage5 + (size_t)b * 512 * N5 + p;

    u64 acc2[56];
    #pragma unroll
    for (int i = 0; i < 56; i++) acc2[i] = 0ull;

    for (int c0 = 0; c0 < 512; c0 += 64) {
        __syncthreads();
        for (int i = tid; i < 64*112; i += 128) {
            int o = i % 112; int c = i / 112;
            ws[c*112 + o] = (o < 64) ? w5[o*512 + c0 + c] : wd[(o-64)*512 + c0 + c];
        }
        __syncthreads();
        const ulonglong2* ws2 = (const ulonglong2*)ws;  // 28 per channel
        for (int c = 0; c < 64; c++) {
            float xv = xin[(size_t)(c0 + c) * N5];
            u64 xv2 = pack2(xv, xv);
            #pragma unroll
            for (int q = 0; q < 28; q++) {
                ulonglong2 wp = ws2[c*28 + q];
                fma2(acc2[q*2+0], xv2, wp.x);
                fma2(acc2[q*2+1], xv2, wp.y);
            }
        }
    }

    // reduced = relu(bn(acc[0:64]))
    float red[64];
    #pragma unroll
    for (int q = 0; q < 32; q++) {
        float2 a = unpack2(acc2[q]);
        red[2*q+0] = fmaxf(a.x * g5[2*q+0] + b5[2*q+0], 0.f);
        red[2*q+1] = fmaxf(a.y * g5[2*q+1] + b5[2*q+1], 0.f);
    }

    // depth logits -> softmax(10*l) -> expected depth over log bins
    float lg[48];
    float m = -1e30f;
    #pragma unroll
    for (int q = 0; q < 24; q++) {
        float2 a = unpack2(acc2[32+q]);
        int j = 2*q;
        lg[j]   = 10.f * (a.x * gd[j]   + bd[j]);
        lg[j+1] = 10.f * (a.y * gd[j+1] + bd[j+1]);
        m = fmaxf(m, fmaxf(lg[j], lg[j+1]));
    }
    const float lstep = 0.08711371545f;  // ln(60)/47
    float sum = 0.f, dsum = 0.f;
    #pragma unroll
    for (int j = 0; j < 48; j++) {
        float e = __expf(lg[j] - m);
        sum  += e;
        dsum += e * __expf((float)j * lstep);
    }
    float depth = dsum / sum;
    depth = fminf(fmaxf(depth, 1.0f), 65.0f);

    // unproject: K^{-1} via adjugate
    const float* K = intr + b * 9;
    float a00=K[0],a01=K[1],a02=K[2],a10=K[3],a11=K[4],a12=K[5],a20=K[6],a21=K[7],a22=K[8];
    float det = a00*(a11*a22 - a12*a21) - a01*(a10*a22 - a12*a20) + a02*(a10*a21 - a11*a20);
    float id = 1.0f / det;
    float i00 = (a11*a22 - a12*a21) * id;
    float i01 = (a02*a21 - a01*a22) * id;
    float i02 = (a01*a12 - a02*a11) * id;
    float i10 = (a12*a20 - a10*a22) * id;
    float i11 = (a00*a22 - a02*a20) * id;
    float i12 = (a02*a10 - a00*a12) * id;
    float i20 = (a10*a21 - a11*a20) * id;
    float i21 = (a01*a20 - a00*a21) * id;
    float i22 = (a00*a11 - a01*a10) * id;

    float py = (float)(p / W5i);
    float px = (float)(p - (p / W5i) * W5i);
    float cx = depth * (i00*px + i01*py + i02);
    float cy = depth * (i10*px + i11*py + i12);
    float cz = depth * (i20*px + i21*py + i22);

    const float* T = extr + b * 16;
    float ex = T[0]*cx + T[1]*cy + T[2]*cz  + T[3];
    float ey = T[4]*cx + T[5]*cy + T[6]*cz  + T[7];
    float ez = T[8]*cx + T[9]*cy + T[10]*cz + T[11];

    bool ev = (ex >= -51.2f) & (ex < 51.2f) & (ey >= -51.2f) & (ey < 51.2f)
            & (ez >= -5.0f)  & (ez < 3.0f);
    int bx = (int)floorf(ex / 0.4f + 64.0f);
    int by = (int)floorf(ey / 0.4f + 64.0f);
    bool gv = (bx >= 0) & (bx < 128) & (by >= 0) & (by < 128);
    if (ev & gv) {
        float wf = __expf(-0.05f * fabsf(ez));
        float* cell = g_bev + (((size_t)b * 128 + by) * 128 + bx) * BEVC;
        #pragma unroll
        for (int o = 0; o < 64; o++)
            atomicAdd(cell + o, red[o] * wf);
    }
}

// ---------------------------------------------------------------------------
// Kernel C: 3x3 conv (64->128) on BEV + BN + ReLU.  Channels-last input tile
// in shared + 32-oc weight tile in shared; f32x2 accumulators over oc pairs.
// ---------------------------------------------------------------------------
__global__ __launch_bounds__(256, 1)
void kC(const float* __restrict__ w, const float* __restrict__ g, const float* __restrict__ bb,
        float* __restrict__ out)
{
    extern __shared__ __align__(16) float sm[];
    float* sin_ = sm;               // [ic 64][cell 340]  (10 x 34 tile)
    float* wsh  = sm + 64*340;      // [(kk*64+ic)*32 + ocl]
    int tid = threadIdx.x;
    int tx = tid & 31, ty = tid >> 5;
    int x0 = blockIdx.x * 32, y0 = blockIdx.y * 8;
    int bz = blockIdx.z;
    int b = bz >> 2;
    int oc0 = (bz & 3) * 32;

    // weights -> shared
    for (int i = tid; i < 18432; i += 256) {
        int ocl = i & 31;
        int t = i >> 5;
        int ic = t & 63;
        int kk = t >> 6;
        wsh[i] = w[((oc0 + ocl) * 64 + ic) * 9 + kk];
    }
    // input tile (with halo, zero padded) -> shared
    const float4* bev4 = (const float4*)g_bev;
    for (int i = tid; i < 5440; i += 256) {           // 340 cells * 16 float4
        int icg = i & 15;
        int cell = i >> 4;
        int iy = cell / 34, ix = cell - iy * 34;
        int gy = y0 + iy - 1, gx = x0 + ix - 1;
        float4 v = make_float4(0.f, 0.f, 0.f, 0.f);
        if (gy >= 0 && gy < 128 && gx >= 0 && gx < 128)
            v = bev4[((((size_t)b * 128 + gy) * 128 + gx) << 4) + icg];
        sin_[(icg*4+0)*340 + cell] = v.x;
        sin_[(icg*4+1)*340 + cell] = v.y;
        sin_[(icg*4+2)*340 + cell] = v.z;
        sin_[(icg*4+3)*340 + cell] = v.w;
    }
    __syncthreads();

    u64 acc2[16];
    #pragma unroll
    for (int q = 0; q < 16; q++) acc2[q] = 0ull;
    const ulonglong2* wsh2 = (const ulonglong2*)wsh;   // 8 per (kk,ic)

    for (int ky = 0; ky < 3; ky++) {
        for (int kx = 0; kx < 3; kx++) {
            int base = (ty + ky) * 34 + tx + kx;
            int kk = ky * 3 + kx;
            #pragma unroll 4
            for (int ic = 0; ic < 64; ic++) {
                float xv = sin_[ic * 340 + base];
                u64 xv2 = pack2(xv, xv);
                #pragma unroll
                for (int q = 0; q < 8; q++) {
                    ulonglong2 wv = wsh2[(kk*64 + ic)*8 + q];
                    fma2(acc2[q*2+0], xv2, wv.x);
                    fma2(acc2[q*2+1], xv2, wv.y);
                }
            }
        }
    }

    float* op = out + (((size_t)b * 128 + oc0) * 128 + (y0 + ty)) * 128 + (x0 + tx);
    #pragma unroll
    for (int q = 0; q < 16; q++) {
        float2 a = unpack2(acc2[q]);
        int o = 2*q;
        op[(size_t)(o+0) * 16384] = fmaxf(a.x * g[oc0 + o]     + bb[oc0 + o],     0.f);
        op[(size_t)(o+1) * 16384] = fmaxf(a.y * g[oc0 + o + 1] + bb[oc0 + o + 1], 0.f);
    }
}

// ---------------------------------------------------------------------------
extern "C" void kernel_launch(void* const* d_in, const int* in_sizes, int n_in,
                              void* d_out, int out_size)
{
    const float* stage1 = (const float*)d_in[0];
    const float* stage5 = (const float*)d_in[1];
    const float* intr   = (const float*)d_in[2];
    const float* extr   = (const float*)d_in[3];
    const float* red1_w = (const float*)d_in[4];
    const float* red1_g = (const float*)d_in[5];
    const float* red1_b = (const float*)d_in[6];
    const float* skip_w = (const float*)d_in[7];
    const float* skip_g = (const float*)d_in[8];
    const float* skip_b = (const float*)d_in[9];
    const float* red5_w = (const float*)d_in[10];
    const float* red5_g = (const float*)d_in[11];
    const float* red5_b = (const float*)d_in[12];
    const float* dep5_w = (const float*)d_in[13];
    const float* dep5_g = (const float*)d_in[14];
    const float* dep5_b = (const float*)d_in[15];
    const float* main_w = (const float*)d_in[16];
    const float* main_g = (const float*)d_in[17];
    const float* main_b = (const float*)d_in[18];

    float* out_main = (float*)d_out;
    float* out_skip = (float*)d_out + OUT_MAIN;

    // zero BEV scratch
    void* bevPtr = nullptr;
    cudaGetSymbolAddress(&bevPtr, g_bev);
    cudaMemsetAsync(bevPtr, 0, sizeof(float) * (size_t)Bn * 128 * 128 * BEVC);

    // skip path
    kA<<<(Bn * HW1) / 128, 128>>>(stage1, red1_w, red1_g, red1_b,
                                  skip_w, skip_g, skip_b, out_skip);

    // lift + scatter
    kB<<<Bn * 88, 128>>>(stage5, red5_w, red5_g, red5_b,
                         dep5_w, dep5_g, dep5_b, intr, extr);

    // BEV conv
    int smem = (64*340 + 18432) * sizeof(float);   // 160768
    cudaFuncSetAttribute(kC, cudaFuncAttributeMaxDynamicSharedMemorySize, smem);
    dim3 gridC(4, 16, Bn * 4);
    kC<<<gridC, 256, smem>>>(main_w, main_g, main_b, out_main);
}

// round 3
// speedup vs baseline: 1.5422x; 1.4271x over previous
#include <cuda_runtime.h>
#include <math.h>

#define Bn 12
#define HW1 45056           // 128*352
#define N5 11264            // 64*176
#define W5i 176
#define BEVC 64
#define OUT_MAIN (12*128*128*128)   // 25165824

typedef unsigned long long u64;

// packed f32x2 helpers (sm_103a)
__device__ __forceinline__ u64 pack2(float lo, float hi) {
    u64 r; asm("mov.b64 %0, {%1, %2};" : "=l"(r) : "f"(lo), "f"(hi)); return r;
}
__device__ __forceinline__ void fma2(u64 &d, u64 a, u64 b) {
    asm("fma.rn.f32x2 %0, %1, %2, %0;" : "+l"(d) : "l"(a), "l"(b));
}
__device__ __forceinline__ float2 unpack2(u64 v) {
    float2 r; asm("mov.b64 {%0, %1}, %2;" : "=f"(r.x), "=f"(r.y) : "l"(v)); return r;
}

// BEV scratch, channels-last: [B][128][128][64]
__device__ float g_bev[Bn * 128 * 128 * BEVC];
// per-pixel scatter target (byte-cell base offset/64 or -1) and weight factor
__device__ int   g_sidx[Bn * N5];
__device__ float g_swf [Bn * N5];

// ---------------------------------------------------------------------------
// Kernel A: fused skip path, 2 pixels per thread.
// ---------------------------------------------------------------------------
__global__ __launch_bounds__(128, 2)
void kA(const float* __restrict__ stage1,
        const float* __restrict__ w1, const float* __restrict__ g1, const float* __restrict__ b1,
        const float* __restrict__ w2, const float* __restrict__ g2, const float* __restrict__ b2,
        float* __restrict__ skip_out)
{
    __shared__ __align__(16) float w1T[64*64];   // [c][o]
    __shared__ __align__(16) float w2T[64*32];   // [o][s]
    __shared__ float sg1[64], sb1[64], sg2[32], sb2[32];
    int tid = threadIdx.x;
    for (int i = tid; i < 64*64; i += 128) { int o = i & 63, c = i >> 6; w1T[c*64+o] = w1[o*64+c]; }
    for (int i = tid; i < 64*32; i += 128) { int s = i & 31, o = i >> 5; w2T[o*32+s] = w2[s*64+o]; }
    if (tid < 64) { sg1[tid] = g1[tid]; sb1[tid] = b1[tid]; }
    if (tid < 32) { sg2[tid] = g2[tid]; sb2[tid] = b2[tid]; }
    __syncthreads();

    // 2 pixels: p and p+128 (HW1 % 256 == 0 so same batch image)
    int gid = blockIdx.x * 256 + tid;
    int b = gid / HW1;
    int p = gid - b * HW1;
    const float* xin = stage1 + (size_t)b * 64 * HW1 + p;

    u64 acc[2][32];
    #pragma unroll
    for (int q = 0; q < 32; q++) { acc[0][q] = 0ull; acc[1][q] = 0ull; }

    const ulonglong2* w1T2 = (const ulonglong2*)w1T;   // 16 per channel
    for (int c = 0; c < 64; c++) {
        const float* xc = xin + (size_t)c * HW1;
        u64 x0 = pack2(xc[0],   xc[0]);
        u64 x1 = pack2(xc[128], xc[128]);
        #pragma unroll
        for (int q = 0; q < 16; q++) {
            ulonglong2 wp = w1T2[c*16 + q];
            fma2(acc[0][q*2+0], x0, wp.x);
            fma2(acc[0][q*2+1], x0, wp.y);
            fma2(acc[1][q*2+0], x1, wp.x);
            fma2(acc[1][q*2+1], x1, wp.y);
        }
    }

    const ulonglong2* w2T2 = (const ulonglong2*)w2T;   // 8 per o
    #pragma unroll
    for (int px = 0; px < 2; px++) {
        u64 sacc2[16];
        #pragma unroll
        for (int s = 0; s < 16; s++) sacc2[s] = 0ull;
        #pragma unroll
        for (int q = 0; q < 32; q++) {
            float2 a = unpack2(acc[px][q]);
            int o = 2*q;
            float v0 = fmaxf(a.x * sg1[o]   + sb1[o],   0.f);
            float v1 = fmaxf(a.y * sg1[o+1] + sb1[o+1], 0.f);
            u64 v0p = pack2(v0, v0);
            u64 v1p = pack2(v1, v1);
            #pragma unroll
            for (int s4 = 0; s4 < 8; s4++) {
                ulonglong2 wp0 = w2T2[o*8 + s4];
                fma2(sacc2[s4*2+0], v0p, wp0.x);
                fma2(sacc2[s4*2+1], v0p, wp0.y);
            }
            #pragma unroll
            for (int s4 = 0; s4 < 8; s4++) {
                ulonglong2 wp1 = w2T2[(o+1)*8 + s4];
                fma2(sacc2[s4*2+0], v1p, wp1.x);
                fma2(sacc2[s4*2+1], v1p, wp1.y);
            }
        }
        float* op = skip_out + (size_t)b * 32 * HW1 + p + px * 128;
        #pragma unroll
        for (int s = 0; s < 16; s++) {
            float2 a = unpack2(sacc2[s]);
            op[(size_t)(2*s+0) * HW1] = fmaxf(a.x * sg2[2*s+0] + sb2[2*s+0], 0.f);
            op[(size_t)(2*s+1) * HW1] = fmaxf(a.y * sg2[2*s+1] + sb2[2*s+1], 0.f);
        }
    }
}

// ---------------------------------------------------------------------------
// Kernel B1: depth head. 48-channel GEMM + softmax depth + geometry.
// Writes per-pixel scatter cell index (or -1) and exp weight.
// ---------------------------------------------------------------------------
__global__ __launch_bounds__(128, 4)
void kB1(const float* __restrict__ stage5,
         const float* __restrict__ wd, const float* __restrict__ gd, const float* __restrict__ bd,
         const float* __restrict__ intr, const float* __restrict__ extr)
{
    __shared__ __align__(16) float ws[64*48];
    __shared__ float sgd[48], sbd[48];
    int tid = threadIdx.x;
    if (tid < 48) { sgd[tid] = gd[tid]; sbd[tid] = bd[tid]; }
    int b = blockIdx.x / 88;
    int p = (blockIdx.x - b * 88) * 128 + tid;
    const float* xin = stage5 + (size_t)b * 512 * N5 + p;

    u64 acc2[24];
    #pragma unroll
    for (int i = 0; i < 24; i++) acc2[i] = 0ull;

    for (int c0 = 0; c0 < 512; c0 += 64) {
        __syncthreads();
        for (int i = tid; i < 64*48; i += 128) {
            int o = i % 48; int c = i / 48;
            ws[c*48 + o] = wd[o*512 + c0 + c];
        }
        __syncthreads();
        const ulonglong2* ws2 = (const ulonglong2*)ws;  // 12 per channel
        for (int c = 0; c < 64; c++) {
            float xv = xin[(size_t)(c0 + c) * N5];
            u64 xv2 = pack2(xv, xv);
            #pragma unroll
            for (int q = 0; q < 12; q++) {
                ulonglong2 wp = ws2[c*12 + q];
                fma2(acc2[q*2+0], xv2, wp.x);
                fma2(acc2[q*2+1], xv2, wp.y);
            }
        }
    }

    // softmax(10 * bn(logits)) -> expected depth over log bins, recompute pass
    float m = -1e30f;
    #pragma unroll
    for (int q = 0; q < 24; q++) {
        float2 a = unpack2(acc2[q]);
        int j = 2*q;
        m = fmaxf(m, fmaxf(10.f * (a.x * sgd[j] + sbd[j]),
                           10.f * (a.y * sgd[j+1] + sbd[j+1])));
    }
    const float lstep = 0.08711371545f;  // ln(60)/47
    float sum = 0.f, dsum = 0.f;
    #pragma unroll
    for (int q = 0; q < 24; q++) {
        float2 a = unpack2(acc2[q]);
        int j = 2*q;
        float l0 = 10.f * (a.x * sgd[j]   + sbd[j]);
        float l1 = 10.f * (a.y * sgd[j+1] + sbd[j+1]);
        float e0 = __expf(l0 - m);
        float e1 = __expf(l1 - m);
        sum  += e0 + e1;
        dsum += e0 * __expf((float)j * lstep) + e1 * __expf((float)(j+1) * lstep);
    }
    float depth = dsum / sum;
    depth = fminf(fmaxf(depth, 1.0f), 65.0f);

    // unproject: K^{-1} via adjugate
    const float* K = intr + b * 9;
    float a00=K[0],a01=K[1],a02=K[2],a10=K[3],a11=K[4],a12=K[5],a20=K[6],a21=K[7],a22=K[8];
    float det = a00*(a11*a22 - a12*a21) - a01*(a10*a22 - a12*a20) + a02*(a10*a21 - a11*a20);
    float id = 1.0f / det;
    float i00 = (a11*a22 - a12*a21) * id;
    float i01 = (a02*a21 - a01*a22) * id;
    float i02 = (a01*a12 - a02*a11) * id;
    float i10 = (a12*a20 - a10*a22) * id;
    float i11 = (a00*a22 - a02*a20) * id;
    float i12 = (a02*a10 - a00*a12) * id;
    float i20 = (a10*a21 - a11*a20) * id;
    float i21 = (a01*a20 - a00*a21) * id;
    float i22 = (a00*a11 - a01*a10) * id;

    float py = (float)(p / W5i);
    float px = (float)(p - (p / W5i) * W5i);
    float cx = depth * (i00*px + i01*py + i02);
    float cy = depth * (i10*px + i11*py + i12);
    float cz = depth * (i20*px + i21*py + i22);

    const float* T = extr + b * 16;
    float ex = T[0]*cx + T[1]*cy + T[2]*cz  + T[3];
    float ey = T[4]*cx + T[5]*cy + T[6]*cz  + T[7];
    float ez = T[8]*cx + T[9]*cy + T[10]*cz + T[11];

    bool ev = (ex >= -51.2f) & (ex < 51.2f) & (ey >= -51.2f) & (ey < 51.2f)
            & (ez >= -5.0f)  & (ez < 3.0f);
    int bx = (int)floorf(ex / 0.4f + 64.0f);
    int by = (int)floorf(ey / 0.4f + 64.0f);
    bool gv = (bx >= 0) & (bx < 128) & (by >= 0) & (by < 128);

    int idx = -1; float wf = 0.f;
    if (ev & gv) {
        idx = ((b * 128 + by) * 128 + bx) * BEVC;
        wf = __expf(-0.05f * fabsf(ez));
    }
    g_sidx[b * N5 + p] = idx;
    g_swf [b * N5 + p] = wf;
}

// ---------------------------------------------------------------------------
// Kernel B2: reduced-feature GEMM (64 out) + scatter-add, 2 pixels/thread.
// ---------------------------------------------------------------------------
__global__ __launch_bounds__(128, 2)
void kB2(const float* __restrict__ stage5,
         const float* __restrict__ w5, const float* __restrict__ g5, const float* __restrict__ b5)
{
    __shared__ __align__(16) float ws[64*64];   // [c][o]
    __shared__ float sg[64], sb[64];
    int tid = threadIdx.x;
    if (tid < 64) { sg[tid] = g5[tid]; sb[tid] = b5[tid]; }
    int b = blockIdx.x / 44;
    int p = (blockIdx.x - b * 44) * 256 + tid;   // pixels p, p+128
    const float* xin = stage5 + (size_t)b * 512 * N5 + p;

    u64 acc[2][32];
    #pragma unroll
    for (int q = 0; q < 32; q++) { acc[0][q] = 0ull; acc[1][q] = 0ull; }

    for (int c0 = 0; c0 < 512; c0 += 64) {
        __syncthreads();
        for (int i = tid; i < 64*64; i += 128) {
            int o = i & 63; int c = i >> 6;
            ws[c*64 + o] = w5[o*512 + c0 + c];
        }
        __syncthreads();
        const ulonglong2* ws2 = (const ulonglong2*)ws;  // 16 per channel
        for (int c = 0; c < 64; c++) {
            const float* xc = xin + (size_t)(c0 + c) * N5;
            u64 x0 = pack2(xc[0],   xc[0]);
            u64 x1 = pack2(xc[128], xc[128]);
            #pragma unroll
            for (int q = 0; q < 16; q++) {
                ulonglong2 wp = ws2[c*16 + q];
                fma2(acc[0][q*2+0], x0, wp.x);
                fma2(acc[0][q*2+1], x0, wp.y);
                fma2(acc[1][q*2+0], x1, wp.x);
                fma2(acc[1][q*2+1], x1, wp.y);
            }
        }
    }

    #pragma unroll
    for (int px = 0; px < 2; px++) {
        int pp = p + px * 128;
        int idx = g_sidx[b * N5 + pp];
        float wf = g_swf[b * N5 + pp];
        if (idx >= 0) {
            float* cell = g_bev + idx;
            #pragma unroll
            for (int q = 0; q < 32; q++) {
                float2 a = unpack2(acc[px][q]);
                float r0 = fmaxf(a.x * sg[2*q+0] + sb[2*q+0], 0.f) * wf;
                float r1 = fmaxf(a.y * sg[2*q+1] + sb[2*q+1], 0.f) * wf;
                atomicAdd(cell + 2*q+0, r0);
                atomicAdd(cell + 2*q+1, r1);
            }
        }
    }
}

// ---------------------------------------------------------------------------
// Kernel C: 3x3 conv (64->128) + BN + ReLU.  32x16 spatial tile, 2 px/thread.
// ---------------------------------------------------------------------------
__global__ __launch_bounds__(256, 1)
void kC(const float* __restrict__ w, const float* __restrict__ g, const float* __restrict__ bb,
        float* __restrict__ out)
{
    extern __shared__ __align__(16) float sm[];
    float* sin_ = sm;               // [ic 64][cell 612]  (18 x 34 tile)
    float* wsh  = sm + 64*612;      // [(kk*64+ic)*32 + ocl]
    int tid = threadIdx.x;
    int tx = tid & 31, ty = tid >> 5;        // ty 0..7
    int x0 = blockIdx.x * 32, y0 = blockIdx.y * 16;
    int bz = blockIdx.z;
    int b = bz >> 2;
    int oc0 = (bz & 3) * 32;

    // weights -> shared
    for (int i = tid; i < 18432; i += 256) {
        int ocl = i & 31;
        int t = i >> 5;
        int ic = t & 63;
        int kk = t >> 6;
        wsh[i] = w[((oc0 + ocl) * 64 + ic) * 9 + kk];
    }
    // input tile (with halo, zero padded) -> shared
    const float4* bev4 = (const float4*)g_bev;
    for (int i = tid; i < 612*16; i += 256) {
        int icg = i & 15;
        int cell = i >> 4;
        int iy = cell / 34, ix = cell - iy * 34;
        int gy = y0 + iy - 1, gx = x0 + ix - 1;
        float4 v = make_float4(0.f, 0.f, 0.f, 0.f);
        if (gy >= 0 && gy < 128 && gx >= 0 && gx < 128)
            v = bev4[((((size_t)b * 128 + gy) * 128 + gx) << 4) + icg];
        sin_[(icg*4+0)*612 + cell] = v.x;
        sin_[(icg*4+1)*612 + cell] = v.y;
        sin_[(icg*4+2)*612 + cell] = v.z;
        sin_[(icg*4+3)*612 + cell] = v.w;
    }
    __syncthreads();

    u64 acc2[2][16];
    #pragma unroll
    for (int q = 0; q < 16; q++) { acc2[0][q] = 0ull; acc2[1][q] = 0ull; }
    const ulonglong2* wsh2 = (const ulonglong2*)wsh;   // 8 per (kk,ic)

    for (int ky = 0; ky < 3; ky++) {
        for (int kx = 0; kx < 3; kx++) {
            int base0 = (ty + ky) * 34 + tx + kx;
            int base1 = base0 + 8 * 34;
            int kk = ky * 3 + kx;
            #pragma unroll 4
            for (int ic = 0; ic < 64; ic++) {
                float xv0 = sin_[ic * 612 + base0];
                float xv1 = sin_[ic * 612 + base1];
                u64 x0p = pack2(xv0, xv0);
                u64 x1p = pack2(xv1, xv1);
                #pragma unroll
                for (int q = 0; q < 8; q++) {
                    ulonglong2 wv = wsh2[(kk*64 + ic)*8 + q];
                    fma2(acc2[0][q*2+0], x0p, wv.x);
                    fma2(acc2[0][q*2+1], x0p, wv.y);
                    fma2(acc2[1][q*2+0], x1p, wv.x);
                    fma2(acc2[1][q*2+1], x1p, wv.y);
                }
            }
        }
    }

    #pragma unroll
    for (int px = 0; px < 2; px++) {
        float* op = out + (((size_t)b * 128 + oc0) * 128 + (y0 + ty + px*8)) * 128 + (x0 + tx);
        #pragma unroll
        for (int q = 0; q < 16; q++) {
            float2 a = unpack2(acc2[px][q]);
            int o = 2*q;
            op[(size_t)(o+0) * 16384] = fmaxf(a.x * g[oc0 + o]     + bb[oc0 + o],     0.f);
            op[(size_t)(o+1) * 16384] = fmaxf(a.y * g[oc0 + o + 1] + bb[oc0 + o + 1], 0.f);
        }
    }
}

// ---------------------------------------------------------------------------
extern "C" void kernel_launch(void* const* d_in, const int* in_sizes, int n_in,
                              void* d_out, int out_size)
{
    const float* stage1 = (const float*)d_in[0];
    const float* stage5 = (const float*)d_in[1];
    const float* intr   = (const float*)d_in[2];
    const float* extr   = (const float*)d_in[3];
    const float* red1_w = (const float*)d_in[4];
    const float* red1_g = (const float*)d_in[5];
    const float* red1_b = (const float*)d_in[6];
    const float* skip_w = (const float*)d_in[7];
    const float* skip_g = (const float*)d_in[8];
    const float* skip_b = (const float*)d_in[9];
    const float* red5_w = (const float*)d_in[10];
    const float* red5_g = (const float*)d_in[11];
    const float* red5_b = (const float*)d_in[12];
    const float* dep5_w = (const float*)d_in[13];
    const float* dep5_g = (const float*)d_in[14];
    const float* dep5_b = (const float*)d_in[15];
    const float* main_w = (const float*)d_in[16];
    const float* main_g = (const float*)d_in[17];
    const float* main_b = (const float*)d_in[18];

    float* out_main = (float*)d_out;
    float* out_skip = (float*)d_out + OUT_MAIN;

    // zero BEV scratch
    void* bevPtr = nullptr;
    cudaGetSymbolAddress(&bevPtr, g_bev);
    cudaMemsetAsync(bevPtr, 0, sizeof(float) * (size_t)Bn * 128 * 128 * BEVC);

    // skip path (2 px/thread)
    kA<<<(Bn * HW1) / 256, 128>>>(stage1, red1_w, red1_g, red1_b,
                                  skip_w, skip_g, skip_b, out_skip);

    // depth head + geometry
    kB1<<<Bn * 88, 128>>>(stage5, dep5_w, dep5_g, dep5_b, intr, extr);

    // reduced features + scatter (2 px/thread)
    kB2<<<Bn * 44, 128>>>(stage5, red5_w, red5_g, red5_b);

    // BEV conv (32x16 tile, 2 px/thread)
    int smem = (64*612 + 18432) * sizeof(float);   // 230400
    cudaFuncSetAttribute(kC, cudaFuncAttributeMaxDynamicSharedMemorySize, smem);
    dim3 gridC(4, 8, Bn * 4);
    kC<<<gridC, 256, smem>>>(main_w, main_g, main_b, out_main);
}